// round 16
// baseline (speedup 1.0000x reference)
#include <cuda_runtime.h>

#define NB   16
#define NC   3
#define NH   768
#define NW   768
#define HW   (NH*NW)        // 589824
#define ND   64
#define PE   (192*192)      // 36864
#define SIDES 32
#define TOPK 400

#define CE_BLOCKS  (NB*HW/4/256)   // 9216
#define AUG_BLOCKS (NB*PE/256)     // 2304

// ---------------- device scratch (static, no allocation) ----------------
__device__ unsigned char g_mask [SIDES*PE];   // 0 none, 1 class-1, 2 class-2
__device__ unsigned      g_keys [SIDES*PE];   // fkey-transformed (ascending order)
__device__ float         g_vec1 [(size_t)SIDES*PE*ND];  // compacted normalized cols
__device__ int           g_cnt1 [SIDES];
__device__ int           g_cnt2 [SIDES];
__device__ float         g_S1   [SIDES*ND];
__device__ float         g_S2   [SIDES*ND];
__device__ unsigned int  g_Tu   [SIDES];
__device__ int           g_needEq[SIDES];
__device__ int           g_eqTaken[SIDES];
__device__ float         g_nll  [NB];
__device__ int           g_vcnt [NB];

// ---------------- helpers ----------------
__device__ __forceinline__ unsigned fkey(float f) {
    unsigned u = __float_as_uint(f);
    return (u & 0x80000000u) ? ~u : (u | 0x80000000u);
}

__device__ __forceinline__ float warpSumF(float v) {
    #pragma unroll
    for (int o = 16; o; o >>= 1) v += __shfl_down_sync(0xffffffffu, v, o);
    return v;
}
__device__ __forceinline__ int warpSumI(int v) {
    #pragma unroll
    for (int o = 16; o; o >>= 1) v += __shfl_down_sync(0xffffffffu, v, o);
    return v;
}

__device__ __forceinline__ int maskval(float a, float b, float c) {
    float m = fmaxf(a, fmaxf(b, c));
    float s = __expf(a - m) + __expf(b - m) + __expf(c - m);
    float conf = 1.0f / s;
    int seg = (a >= b) ? (a >= c ? 0 : 2) : (b >= c ? 1 : 2);
    return (seg == 1 && conf > 0.8f) ? 1 : ((seg == 2 && conf > 0.6f) ? 2 : 0);
}

__device__ __forceinline__ float nll_one(float a, float b, float c, int l, int& vc) {
    if (l == 255) return 0.0f;
    float m = fmaxf(a, fmaxf(b, c));
    float lse = m + __logf(__expf(a - m) + __expf(b - m) + __expf(c - m));
    float xl = (l == 0) ? a : ((l == 1) ? b : c);
    vc++;
    return lse - xl;
}

// ---------------- kernels ----------------
__global__ void k_init() {
    int t = threadIdx.x;
    for (int i = t; i < SIDES*ND; i += blockDim.x) { g_S1[i] = 0.f; g_S2[i] = 0.f; }
    if (t < SIDES) { g_cnt1[t] = 0; g_cnt2[t] = 0; g_eqTaken[t] = 0; }
    if (t < NB)    { g_nll[t] = 0.f; g_vcnt[t] = 0; }
}

// Fused: CE + mask (sides 0..15); aug mask (sides 16..31).
__global__ void k_cea(const float* __restrict__ outp, const int* __restrict__ lbl,
                      const float* __restrict__ outa) {
    if (blockIdx.x < CE_BLOCKS) {
        int t = blockIdx.x * blockDim.x + threadIdx.x;   // group-of-4 index
        int b = t / (HW/4);
        int g = t % (HW/4);
        int p = g * 4;                                   // first pixel of group
        const float4* c0 = (const float4*)(outp + (size_t)b*NC*HW);
        const float4* c1 = (const float4*)(outp + (size_t)b*NC*HW + HW);
        const float4* c2 = (const float4*)(outp + (size_t)b*NC*HW + 2*HW);
        float4 x0 = c0[g], x1 = c1[g], x2 = c2[g];
        int4 l4 = ((const int4*)(lbl + (size_t)b*HW))[g];

        int vc = 0;
        float nll = 0.f;
        nll += nll_one(x0.x, x1.x, x2.x, l4.x, vc);
        nll += nll_one(x0.y, x1.y, x2.y, l4.y, vc);
        nll += nll_one(x0.z, x1.z, x2.z, l4.z, vc);
        nll += nll_one(x0.w, x1.w, x2.w, l4.w, vc);

        int h = p / NW;
        if ((h & 3) == 0) {                              // w%4==0 always
            int dp = (h >> 2) * 192 + ((p % NW) >> 2);
            g_mask[b*PE + dp] = (unsigned char)maskval(x0.x, x1.x, x2.x);
        }

        __shared__ float s_n[8];
        __shared__ int   s_c[8];
        float wn = warpSumF(nll);
        int   wc = warpSumI(vc);
        int lane = threadIdx.x & 31, wid = threadIdx.x >> 5;
        if (lane == 0) { s_n[wid] = wn; s_c[wid] = wc; }
        __syncthreads();
        if (wid == 0) {
            float vn = (lane < 8) ? s_n[lane] : 0.f;
            int   vcc = (lane < 8) ? s_c[lane] : 0;
            vn = warpSumF(vn); vcc = warpSumI(vcc);
            if (lane == 0) { atomicAdd(&g_nll[b], vn); atomicAdd(&g_vcnt[b], vcc); }
        }
    } else {
        int t = (blockIdx.x - CE_BLOCKS) * blockDim.x + threadIdx.x;  // 16*PE threads
        int b = t / PE, dp = t % PE;
        int i = dp / 192, j = dp % 192;
        const float* base = outa + (size_t)b*NC*HW + (size_t)(i*4)*NW + j*4;
        float a0 = base[0], a1 = base[HW], a2 = base[2*HW];
        g_mask[(16+b)*PE + dp] = (unsigned char)maskval(a0, a1, a2);
    }
}

// Embedding pass: float4 loads, 64B contiguous per line-touch (2x wavefront
// bytes vs scalar). lane = pixq*8 + c8: 4 consecutive pixels, 8 channels.
// NO launch_bounds: let ptxas keep e[8] float4 in registers (no spills).
// grid (72, 32), 128 threads, 512 px/block.
__global__ void k_embed(const float* __restrict__ emb,
                        const float* __restrict__ emba) {
    int side = blockIdx.y;
    const float* base = (side < 16) ? (emb  + (size_t)side      * ND * PE)
                                    : (emba + (size_t)(side-16) * ND * PE);
    int lane = threadIdx.x & 31;
    int warp = threadIdx.x >> 5;
    int c8   = lane & 7;
    int pixq = lane >> 3;
    int warpbase = blockIdx.x * 512 + warp * 128;

    float acc[8];
    #pragma unroll
    for (int j = 0; j < 8; j++) acc[j] = 0.f;
    int c2loc = 0;

    for (int it = 0; it < 8; it++) {
        int p0 = warpbase + it * 16 + pixq * 4;
        uchar4 mk = *(const uchar4*)(g_mask + side*PE + p0);

        float4 e[8];
        #pragma unroll
        for (int j = 0; j < 8; j++)
            e[j] = *(const float4*)(base + (size_t)(8*j + c8) * PE + p0);

        float4 sq = make_float4(0.f,0.f,0.f,0.f);
        float4 sm = make_float4(0.f,0.f,0.f,0.f);
        #pragma unroll
        for (int j = 0; j < 8; j++) {
            sq.x += e[j].x*e[j].x; sq.y += e[j].y*e[j].y;
            sq.z += e[j].z*e[j].z; sq.w += e[j].w*e[j].w;
            sm.x += e[j].x; sm.y += e[j].y; sm.z += e[j].z; sm.w += e[j].w;
        }
        #pragma unroll
        for (int o = 1; o < 8; o <<= 1) {
            sq.x += __shfl_xor_sync(0xffffffffu, sq.x, o);
            sq.y += __shfl_xor_sync(0xffffffffu, sq.y, o);
            sq.z += __shfl_xor_sync(0xffffffffu, sq.z, o);
            sq.w += __shfl_xor_sync(0xffffffffu, sq.w, o);
            sm.x += __shfl_xor_sync(0xffffffffu, sm.x, o);
            sm.y += __shfl_xor_sync(0xffffffffu, sm.y, o);
            sm.z += __shfl_xor_sync(0xffffffffu, sm.z, o);
            sm.w += __shfl_xor_sync(0xffffffffu, sm.w, o);
        }
        float4 inv = make_float4(rsqrtf(sq.x), rsqrtf(sq.y), rsqrtf(sq.z), rsqrtf(sq.w));
        float4 f = make_float4(mk.x == 2 ? inv.x : 0.f, mk.y == 2 ? inv.y : 0.f,
                               mk.z == 2 ? inv.z : 0.f, mk.w == 2 ? inv.w : 0.f);
        #pragma unroll
        for (int j = 0; j < 8; j++)
            acc[j] += e[j].x*f.x + e[j].y*f.y + e[j].z*f.z + e[j].w*f.w;
        if (c8 == 0)
            c2loc += (mk.x==2) + (mk.y==2) + (mk.z==2) + (mk.w==2);

        int m1x = mk.x==1, m1y = mk.y==1, m1z = mk.z==1, m1w = mk.w==1;
        int cnt = (c8 == 0) ? (m1x + m1y + m1z + m1w) : 0;
        unsigned bal1 = __ballot_sync(0xffffffffu, cnt != 0);
        if (bal1) {
            int pre = cnt;
            #pragma unroll
            for (int o = 1; o < 32; o <<= 1) {
                int t2 = __shfl_up_sync(0xffffffffu, pre, o);
                if (lane >= o) pre += t2;
            }
            int total = __shfl_sync(0xffffffffu, pre, 31);
            int basei = 0;
            if (lane == 31) basei = atomicAdd(&g_cnt1[side], total);
            basei = __shfl_sync(0xffffffffu, basei, 31);
            int s0 = -1, s1 = -1, s2 = -1, s3 = -1;
            if (c8 == 0) {
                int o2 = basei + pre - cnt;
                if (m1x) s0 = o2++;
                if (m1y) s1 = o2++;
                if (m1z) s2 = o2++;
                if (m1w) s3 = o2++;
                if (s0 >= 0) g_keys[side*PE + s0] = fkey(sm.x * (1.0f/64.0f));
                if (s1 >= 0) g_keys[side*PE + s1] = fkey(sm.y * (1.0f/64.0f));
                if (s2 >= 0) g_keys[side*PE + s2] = fkey(sm.z * (1.0f/64.0f));
                if (s3 >= 0) g_keys[side*PE + s3] = fkey(sm.w * (1.0f/64.0f));
            }
            int src = lane & ~7;
            s0 = __shfl_sync(0xffffffffu, s0, src);
            s1 = __shfl_sync(0xffffffffu, s1, src);
            s2 = __shfl_sync(0xffffffffu, s2, src);
            s3 = __shfl_sync(0xffffffffu, s3, src);
            // write compacted normalized vectors straight from registers
            if (s0 >= 0) {
                float* v = g_vec1 + ((size_t)side*PE + s0) * ND;
                #pragma unroll
                for (int j = 0; j < 8; j++) v[8*j + c8] = e[j].x * inv.x;
            }
            if (s1 >= 0) {
                float* v = g_vec1 + ((size_t)side*PE + s1) * ND;
                #pragma unroll
                for (int j = 0; j < 8; j++) v[8*j + c8] = e[j].y * inv.y;
            }
            if (s2 >= 0) {
                float* v = g_vec1 + ((size_t)side*PE + s2) * ND;
                #pragma unroll
                for (int j = 0; j < 8; j++) v[8*j + c8] = e[j].z * inv.z;
            }
            if (s3 >= 0) {
                float* v = g_vec1 + ((size_t)side*PE + s3) * ND;
                #pragma unroll
                for (int j = 0; j < 8; j++) v[8*j + c8] = e[j].w * inv.w;
            }
        }
    }

    // S2: acc[j] holds channel 8j+c8 summed over this lane's pixels; reduce pixq.
    #pragma unroll
    for (int j = 0; j < 8; j++) {
        float v = acc[j];
        v += __shfl_xor_sync(0xffffffffu, v, 8);
        v += __shfl_xor_sync(0xffffffffu, v, 16);
        if (lane < 8) atomicAdd(&g_S2[side*ND + 8*j + lane], v);
    }
    int cs = warpSumI(c2loc);
    if (lane == 0 && cs) atomicAdd(&g_cnt2[side], cs);
}

// Exact 400th-smallest key per side: 4 byte-passes, 1024 threads,
// warp-parallel bin scan.
__global__ __launch_bounds__(1024) void k_select() {
    int side = blockIdx.x;
    __shared__ int hist[256];
    __shared__ unsigned sh_prefix;
    __shared__ int sh_k;
    int tid = threadIdx.x;
    int lane = tid & 31, warp = tid >> 5;

    int n = g_cnt1[side];
    if (n <= TOPK) {
        if (tid == 0) { g_Tu[side] = 0xFFFFFFFFu; g_needEq[side] = 0; }
        return;
    }
    if (tid == 0) { sh_prefix = 0u; sh_k = TOPK; }
    __syncthreads();
    unsigned done_mask = 0u;
    for (int shift = 24; shift >= 0; shift -= 8) {
        for (int i = tid; i < 256; i += blockDim.x) hist[i] = 0;
        __syncthreads();
        unsigned pref = sh_prefix;
        for (int i = tid; i < n; i += blockDim.x) {
            unsigned u = g_keys[side*PE + i];
            if ((u & done_mask) == pref) atomicAdd(&hist[(u >> shift) & 0xFF], 1);
        }
        __syncthreads();
        if (warp == 0) {
            int s[8]; int tot = 0;
            #pragma unroll
            for (int j = 0; j < 8; j++) { s[j] = hist[lane*8 + j]; tot += s[j]; }
            int pre = tot;
            #pragma unroll
            for (int o = 1; o < 32; o <<= 1) {
                int t2 = __shfl_up_sync(0xffffffffu, pre, o);
                if (lane >= o) pre += t2;
            }
            int excl = pre - tot;
            int k = sh_k;
            if (excl < k && k <= excl + tot) {
                int kk = k - excl;
                int bin = lane * 8;
                #pragma unroll
                for (int j = 0; j < 8; j++) {
                    if (kk <= s[j]) { bin = lane*8 + j; break; }
                    kk -= s[j];
                }
                sh_prefix = pref | ((unsigned)bin << shift);
                sh_k = kk;
            }
        }
        done_mask |= (0xFFu << shift);
        __syncthreads();
    }
    if (tid == 0) { g_Tu[side] = sh_prefix; g_needEq[side] = sh_k; }
}

// Gather from COMPACTED vectors: 64 warps per side, coalesced 256B reads,
// register accumulation, 2 spread atomics per warp at the end.
__global__ void k_gather() {
    int side = blockIdx.y;
    int n = g_cnt1[side];
    unsigned T = g_Tu[side];
    int needEq = g_needEq[side];
    int lane = threadIdx.x & 31;
    int warp = threadIdx.x >> 5;
    int gwarp = blockIdx.x * (blockDim.x >> 5) + warp;   // 0..63
    const int TOTW = 64;

    float a0 = 0.f, a1 = 0.f;
    for (int i = gwarp; i < n; i += TOTW) {
        unsigned u = g_keys[side*PE + i];
        int take;
        if (lane == 0) {
            take = (u < T) ? 1 : 0;
            if (!take && u == T && needEq > 0) {
                int slot = atomicAdd(&g_eqTaken[side], 1);
                take = (slot < needEq) ? 1 : 0;
            }
        }
        take = __shfl_sync(0xffffffffu, take, 0);
        if (take) {
            const float* v = g_vec1 + ((size_t)side * PE + i) * ND;
            a0 += v[lane];
            a1 += v[lane + 32];
        }
    }
    atomicAdd(&g_S1[side*ND + lane], a0);
    atomicAdd(&g_S1[side*ND + lane + 32], a1);
}

// Final scalar assembly.
__global__ void k_final(float* __restrict__ out, int out_size) {
    int b = threadIdx.x;   // 32 lanes, b<16 active
    float contrib = 0.f, ce = 0.f;
    int vflag = 0;
    if (b < NB) {
        float dot1 = 0.f, dot2 = 0.f;
        #pragma unroll
        for (int d = 0; d < ND; d++) {
            dot1 += g_S1[b*ND + d] * g_S1[(16+b)*ND + d];
            dot2 += g_S2[b*ND + d] * g_S2[(16+b)*ND + d];
        }
        int c2 = g_cnt2[b], c2a = g_cnt2[16+b];
        float d1 = 1.0f - dot1 * (1.0f / ((float)TOPK * (float)TOPK));
        float d2 = 1.0f - dot2 * (1.0f / (float)max(c2,1)) * (1.0f / (float)max(c2a,1));
        bool v1 = (g_cnt1[b] > TOPK) && (g_cnt1[16+b] > TOPK);
        bool v2 = (c2 > 0) && (c2a > 0);
        contrib = (v1 ? d1 : 0.f) + (v2 ? d2 : 0.f);
        vflag = (int)v1 + (int)v2;
        ce = g_nll[b] / fmaxf((float)g_vcnt[b], 1.0f);
    }
    contrib = warpSumF(contrib);
    ce = warpSumF(ce);
    vflag = warpSumI(vflag);
    if (threadIdx.x == 0) {
        float loss_ce = ce * (1.0f / (float)NB);
        float lm = contrib / fmaxf((float)vflag, 1.0f);
        float loss = loss_ce + 2.0f * lm;
        out[0] = loss;
        if (out_size > 1) out[1] = loss_ce;
        if (out_size > 2) out[2] = lm;
    }
}

extern "C" void kernel_launch(void* const* d_in, const int* in_sizes, int n_in,
                              void* d_out, int out_size) {
    const float* outputs        = (const float*)d_in[0];
    const float* embeddings     = (const float*)d_in[1];
    const int*   class_labels   = (const int*)  d_in[2];
    const float* outputs_aug    = (const float*)d_in[3];
    const float* embeddings_aug = (const float*)d_in[4];
    // d_in[5] (class_labels_aug) is unused by the loss.

    k_init<<<1, 1024>>>();
    k_cea <<<CE_BLOCKS + AUG_BLOCKS, 256>>>(outputs, class_labels, outputs_aug);
    k_embed<<<dim3(72, SIDES), 128>>>(embeddings, embeddings_aug);
    k_select<<<SIDES, 1024>>>();
    k_gather<<<dim3(8, SIDES), 256>>>();
    k_final<<<1, 32>>>((float*)d_out, out_size);
}

// round 17
// speedup vs baseline: 1.7427x; 1.7427x over previous
#include <cuda_runtime.h>

#define NB   16
#define NC   3
#define NH   768
#define NW   768
#define HW   (NH*NW)        // 589824
#define ND   64
#define PE   (192*192)      // 36864
#define SIDES 32
#define TOPK 400

#define CE_BLOCKS  (NB*HW/4/256)   // 9216
#define AUG_BLOCKS (NB*PE/256)     // 2304

// ---------------- device scratch (static, no allocation) ----------------
__device__ unsigned char g_mask [SIDES*PE];   // 0 none, 1 class-1, 2 class-2
__device__ unsigned      g_keys [SIDES*PE];   // fkey-transformed (ascending order)
__device__ float         g_vec1 [(size_t)SIDES*PE*ND];  // compacted normalized cols
__device__ int           g_cnt1 [SIDES];
__device__ int           g_cnt2 [SIDES];
__device__ float         g_S1   [SIDES*ND];
__device__ float         g_S2   [SIDES*ND];
__device__ unsigned int  g_Tu   [SIDES];
__device__ int           g_needEq[SIDES];
__device__ int           g_eqTaken[SIDES];
__device__ float         g_nll  [NB];
__device__ int           g_vcnt [NB];

// ---------------- helpers ----------------
__device__ __forceinline__ unsigned fkey(float f) {
    unsigned u = __float_as_uint(f);
    return (u & 0x80000000u) ? ~u : (u | 0x80000000u);
}

__device__ __forceinline__ float warpSumF(float v) {
    #pragma unroll
    for (int o = 16; o; o >>= 1) v += __shfl_down_sync(0xffffffffu, v, o);
    return v;
}
__device__ __forceinline__ int warpSumI(int v) {
    #pragma unroll
    for (int o = 16; o; o >>= 1) v += __shfl_down_sync(0xffffffffu, v, o);
    return v;
}

__device__ __forceinline__ int maskval(float a, float b, float c) {
    float m = fmaxf(a, fmaxf(b, c));
    float s = __expf(a - m) + __expf(b - m) + __expf(c - m);
    float conf = 1.0f / s;
    int seg = (a >= b) ? (a >= c ? 0 : 2) : (b >= c ? 1 : 2);
    return (seg == 1 && conf > 0.8f) ? 1 : ((seg == 2 && conf > 0.6f) ? 2 : 0);
}

__device__ __forceinline__ float nll_one(float a, float b, float c, int l, int& vc) {
    if (l == 255) return 0.0f;
    float m = fmaxf(a, fmaxf(b, c));
    float lse = m + __logf(__expf(a - m) + __expf(b - m) + __expf(c - m));
    float xl = (l == 0) ? a : ((l == 1) ? b : c);
    vc++;
    return lse - xl;
}

// ---------------- kernels ----------------
__global__ void k_init() {
    int t = threadIdx.x;
    for (int i = t; i < SIDES*ND; i += blockDim.x) { g_S1[i] = 0.f; g_S2[i] = 0.f; }
    if (t < SIDES) { g_cnt1[t] = 0; g_cnt2[t] = 0; g_eqTaken[t] = 0; }
    if (t < NB)    { g_nll[t] = 0.f; g_vcnt[t] = 0; }
}

// Fused: CE + mask (sides 0..15); aug mask (sides 16..31).
__global__ void k_cea(const float* __restrict__ outp, const int* __restrict__ lbl,
                      const float* __restrict__ outa) {
    if (blockIdx.x < CE_BLOCKS) {
        int t = blockIdx.x * blockDim.x + threadIdx.x;   // group-of-4 index
        int b = t / (HW/4);
        int g = t % (HW/4);
        int p = g * 4;                                   // first pixel of group
        const float4* c0 = (const float4*)(outp + (size_t)b*NC*HW);
        const float4* c1 = (const float4*)(outp + (size_t)b*NC*HW + HW);
        const float4* c2 = (const float4*)(outp + (size_t)b*NC*HW + 2*HW);
        float4 x0 = c0[g], x1 = c1[g], x2 = c2[g];
        int4 l4 = ((const int4*)(lbl + (size_t)b*HW))[g];

        int vc = 0;
        float nll = 0.f;
        nll += nll_one(x0.x, x1.x, x2.x, l4.x, vc);
        nll += nll_one(x0.y, x1.y, x2.y, l4.y, vc);
        nll += nll_one(x0.z, x1.z, x2.z, l4.z, vc);
        nll += nll_one(x0.w, x1.w, x2.w, l4.w, vc);

        int h = p / NW;
        if ((h & 3) == 0) {                              // w%4==0 always
            int dp = (h >> 2) * 192 + ((p % NW) >> 2);
            g_mask[b*PE + dp] = (unsigned char)maskval(x0.x, x1.x, x2.x);
        }

        __shared__ float s_n[8];
        __shared__ int   s_c[8];
        float wn = warpSumF(nll);
        int   wc = warpSumI(vc);
        int lane = threadIdx.x & 31, wid = threadIdx.x >> 5;
        if (lane == 0) { s_n[wid] = wn; s_c[wid] = wc; }
        __syncthreads();
        if (wid == 0) {
            float vn = (lane < 8) ? s_n[lane] : 0.f;
            int   vcc = (lane < 8) ? s_c[lane] : 0;
            vn = warpSumF(vn); vcc = warpSumI(vcc);
            if (lane == 0) { atomicAdd(&g_nll[b], vn); atomicAdd(&g_vcnt[b], vcc); }
        }
    } else {
        int t = (blockIdx.x - CE_BLOCKS) * blockDim.x + threadIdx.x;  // 16*PE threads
        int b = t / PE, dp = t % PE;
        int i = dp / 192, j = dp % 192;
        const float* base = outa + (size_t)b*NC*HW + (size_t)(i*4)*NW + j*4;
        float a0 = base[0], a1 = base[HW], a2 = base[2*HW];
        g_mask[(16+b)*PE + dp] = (unsigned char)maskval(a0, a1, a2);
    }
}

// Embedding pass (R11-proven scalar 4-way channel split) + group skip:
// 4 lanes per pixel, 16 channels each; iteration covers 8 consecutive pixels
// (= one 32B DRAM sector per channel). If NO pixel in the group is masked,
// skip all 64 sector loads + shuffles. grid (72, 32), 128 thr, 512 px/block.
__global__ __launch_bounds__(128, 8) void k_embed(const float* __restrict__ emb,
                                                  const float* __restrict__ emba) {
    int side = blockIdx.y;
    const float* base = (side < 16) ? (emb  + (size_t)side      * ND * PE)
                                    : (emba + (size_t)(side-16) * ND * PE);
    int lane = threadIdx.x & 31;
    int warp = threadIdx.x >> 5;
    int par  = lane & 3;                           // channel offset 0..3
    int pixl = lane >> 2;                          // 0..7
    int pbase0 = blockIdx.x * 512 + warp * 128;

    float acc[16];
    #pragma unroll
    for (int k = 0; k < 16; k++) acc[k] = 0.f;
    int c2loc = 0;

    for (int it = 0; it < 16; it++) {
        int p = pbase0 + it * 8 + pixl;
        unsigned char mk = g_mask[side*PE + p];
        bool m1 = (mk == 1);
        bool m2 = (mk == 2);

        // group skip: 8 pixels (one 32B sector per channel) with no mask
        unsigned any = __ballot_sync(0xffffffffu, mk != 0);
        if (!any) continue;

        const float* col = base + (size_t)par * PE + p;
        float e[16];
        #pragma unroll
        for (int k = 0; k < 16; k++) e[k] = col[(size_t)(4*k) * PE];

        float sum = 0.f, sq = 0.f;
        #pragma unroll
        for (int k = 0; k < 16; k++) { sum += e[k]; sq += e[k]*e[k]; }

        // reduce within the 4-lane pixel group
        sq += __shfl_xor_sync(0xffffffffu, sq, 1);
        sq += __shfl_xor_sync(0xffffffffu, sq, 2);
        float inv = rsqrtf(sq);
        float f = m2 ? inv : 0.f;
        #pragma unroll
        for (int k = 0; k < 16; k++) acc[k] += e[k] * f;
        c2loc += (int)(m2 && par == 0);

        // class-1 push: key from lane par==0 (warp-aggregated), vector from all 4 lanes
        bool push = m1 && (par == 0);
        unsigned bal = __ballot_sync(0xffffffffu, push);
        if (bal) {
            float sf = sum;
            sf += __shfl_xor_sync(0xffffffffu, sf, 1);
            sf += __shfl_xor_sync(0xffffffffu, sf, 2);
            int leader = __ffs(bal) - 1;
            int cnt = __popc(bal);
            int basei = 0;
            if (lane == leader) basei = atomicAdd(&g_cnt1[side], cnt);
            basei = __shfl_sync(0xffffffffu, basei, leader);
            int off = -1;
            if (push) {
                off = basei + __popc(bal & ((1u << lane) - 1u));
                g_keys[side*PE + off] = fkey(sf * (1.0f / 64.0f));
            }
            // broadcast slot to the 4 lanes of each pushing pixel group
            int goff = __shfl_sync(0xffffffffu, off, lane & ~3);
            if (m1) {
                float* v = g_vec1 + ((size_t)side * PE + goff) * ND;
                #pragma unroll
                for (int k = 0; k < 16; k++) v[4*k + par] = e[k] * inv;
            }
        }
    }

    // Reduce over the 8 pixel-lanes of the same par; lanes 0..3 hold 4k+par.
    #pragma unroll
    for (int k = 0; k < 16; k++) {
        float v = acc[k];
        v += __shfl_xor_sync(0xffffffffu, v, 4);
        v += __shfl_xor_sync(0xffffffffu, v, 8);
        v += __shfl_xor_sync(0xffffffffu, v, 16);
        if (lane < 4) atomicAdd(&g_S2[side*ND + 4*k + lane], v);
    }
    int cs = warpSumI(c2loc);
    if (lane == 0 && cs) atomicAdd(&g_cnt2[side], cs);
}

// Exact 400th-smallest key per side: 4 byte-passes, 1024 threads,
// warp-parallel bin scan.
__global__ __launch_bounds__(1024) void k_select() {
    int side = blockIdx.x;
    __shared__ int hist[256];
    __shared__ unsigned sh_prefix;
    __shared__ int sh_k;
    int tid = threadIdx.x;
    int lane = tid & 31, warp = tid >> 5;

    int n = g_cnt1[side];
    if (n <= TOPK) {
        if (tid == 0) { g_Tu[side] = 0xFFFFFFFFu; g_needEq[side] = 0; }
        return;
    }
    if (tid == 0) { sh_prefix = 0u; sh_k = TOPK; }
    __syncthreads();
    unsigned done_mask = 0u;
    for (int shift = 24; shift >= 0; shift -= 8) {
        for (int i = tid; i < 256; i += blockDim.x) hist[i] = 0;
        __syncthreads();
        unsigned pref = sh_prefix;
        for (int i = tid; i < n; i += blockDim.x) {
            unsigned u = g_keys[side*PE + i];
            if ((u & done_mask) == pref) atomicAdd(&hist[(u >> shift) & 0xFF], 1);
        }
        __syncthreads();
        if (warp == 0) {
            int s[8]; int tot = 0;
            #pragma unroll
            for (int j = 0; j < 8; j++) { s[j] = hist[lane*8 + j]; tot += s[j]; }
            int pre = tot;
            #pragma unroll
            for (int o = 1; o < 32; o <<= 1) {
                int t2 = __shfl_up_sync(0xffffffffu, pre, o);
                if (lane >= o) pre += t2;
            }
            int excl = pre - tot;
            int k = sh_k;
            if (excl < k && k <= excl + tot) {
                int kk = k - excl;
                int bin = lane * 8;
                #pragma unroll
                for (int j = 0; j < 8; j++) {
                    if (kk <= s[j]) { bin = lane*8 + j; break; }
                    kk -= s[j];
                }
                sh_prefix = pref | ((unsigned)bin << shift);
                sh_k = kk;
            }
        }
        done_mask |= (0xFFu << shift);
        __syncthreads();
    }
    if (tid == 0) { g_Tu[side] = sh_prefix; g_needEq[side] = sh_k; }
}

// Gather from COMPACTED vectors: 64 warps per side, coalesced 256B reads,
// register accumulation, 2 spread atomics per warp at the end.
__global__ void k_gather() {
    int side = blockIdx.y;
    int n = g_cnt1[side];
    unsigned T = g_Tu[side];
    int needEq = g_needEq[side];
    int lane = threadIdx.x & 31;
    int warp = threadIdx.x >> 5;
    int gwarp = blockIdx.x * (blockDim.x >> 5) + warp;   // 0..63
    const int TOTW = 64;

    float a0 = 0.f, a1 = 0.f;
    for (int i = gwarp; i < n; i += TOTW) {
        unsigned u = g_keys[side*PE + i];
        int take;
        if (lane == 0) {
            take = (u < T) ? 1 : 0;
            if (!take && u == T && needEq > 0) {
                int slot = atomicAdd(&g_eqTaken[side], 1);
                take = (slot < needEq) ? 1 : 0;
            }
        }
        take = __shfl_sync(0xffffffffu, take, 0);
        if (take) {
            const float* v = g_vec1 + ((size_t)side * PE + i) * ND;
            a0 += v[lane];
            a1 += v[lane + 32];
        }
    }
    atomicAdd(&g_S1[side*ND + lane], a0);
    atomicAdd(&g_S1[side*ND + lane + 32], a1);
}

// Final scalar assembly.
__global__ void k_final(float* __restrict__ out, int out_size) {
    int b = threadIdx.x;   // 32 lanes, b<16 active
    float contrib = 0.f, ce = 0.f;
    int vflag = 0;
    if (b < NB) {
        float dot1 = 0.f, dot2 = 0.f;
        #pragma unroll
        for (int d = 0; d < ND; d++) {
            dot1 += g_S1[b*ND + d] * g_S1[(16+b)*ND + d];
            dot2 += g_S2[b*ND + d] * g_S2[(16+b)*ND + d];
        }
        int c2 = g_cnt2[b], c2a = g_cnt2[16+b];
        float d1 = 1.0f - dot1 * (1.0f / ((float)TOPK * (float)TOPK));
        float d2 = 1.0f - dot2 * (1.0f / (float)max(c2,1)) * (1.0f / (float)max(c2a,1));
        bool v1 = (g_cnt1[b] > TOPK) && (g_cnt1[16+b] > TOPK);
        bool v2 = (c2 > 0) && (c2a > 0);
        contrib = (v1 ? d1 : 0.f) + (v2 ? d2 : 0.f);
        vflag = (int)v1 + (int)v2;
        ce = g_nll[b] / fmaxf((float)g_vcnt[b], 1.0f);
    }
    contrib = warpSumF(contrib);
    ce = warpSumF(ce);
    vflag = warpSumI(vflag);
    if (threadIdx.x == 0) {
        float loss_ce = ce * (1.0f / (float)NB);
        float lm = contrib / fmaxf((float)vflag, 1.0f);
        float loss = loss_ce + 2.0f * lm;
        out[0] = loss;
        if (out_size > 1) out[1] = loss_ce;
        if (out_size > 2) out[2] = lm;
    }
}

extern "C" void kernel_launch(void* const* d_in, const int* in_sizes, int n_in,
                              void* d_out, int out_size) {
    const float* outputs        = (const float*)d_in[0];
    const float* embeddings     = (const float*)d_in[1];
    const int*   class_labels   = (const int*)  d_in[2];
    const float* outputs_aug    = (const float*)d_in[3];
    const float* embeddings_aug = (const float*)d_in[4];
    // d_in[5] (class_labels_aug) is unused by the loss.

    k_init<<<1, 1024>>>();
    k_cea <<<CE_BLOCKS + AUG_BLOCKS, 256>>>(outputs, class_labels, outputs_aug);
    k_embed<<<dim3(72, SIDES), 128>>>(embeddings, embeddings_aug);
    k_select<<<SIDES, 1024>>>();
    k_gather<<<dim3(8, SIDES), 256>>>();
    k_final<<<1, 32>>>((float*)d_out, out_size);
}